// round 4
// baseline (speedup 1.0000x reference)
#include <cuda_runtime.h>
#include <cstdint>
#include <cstddef>

#define N_NODES 4096
#define IN_FEAT 256
#define N_HEADS 8
#define N_HIDDEN 32
#define OUT_FEAT 256   // N_HEADS * N_HIDDEN

// Scratch (static __device__ globals: allocation-free per harness rules)
__device__ float d_g[N_NODES * OUT_FEAT];      // 4 MB: g = h @ W^T
__device__ float d_si[N_NODES * N_HEADS];      // s_i[n][h]
__device__ float d_sj[N_NODES * N_HEADS];      // s_j[n][h]

// ---------------------------------------------------------------------------
// Kernel 1: g = h @ W^T   (fp32 tiled GEMM, C[4096,256], K=256)
// BM=64, BN=64, BK=32, 256 threads, 4x4 microtile per thread.
// ---------------------------------------------------------------------------
__global__ __launch_bounds__(256) void gemm_hW_kernel(const float* __restrict__ h,
                                                      const float* __restrict__ W) {
    __shared__ __align__(16) float As[32 * 68];  // [kk][row], padded stride 68
    __shared__ __align__(16) float Bs[32 * 68];

    const int n0 = blockIdx.x * 64;
    const int o0 = blockIdx.y * 64;
    const int t  = threadIdx.x;
    const int tx = t & 15;       // 16 col-groups
    const int ty = t >> 4;       // 16 row-groups

    float acc[4][4] = {};

    for (int k0 = 0; k0 < IN_FEAT; k0 += 32) {
#pragma unroll
        for (int rep = 0; rep < 2; rep++) {
            int idx = t + rep * 256;          // 0..511
            int r   = idx >> 3;               // 0..63
            int c4  = idx & 7;                // float4 column group
            float4 av = *(const float4*)(h + (size_t)(n0 + r) * IN_FEAT + k0 + c4 * 4);
            As[(c4 * 4 + 0) * 68 + r] = av.x;
            As[(c4 * 4 + 1) * 68 + r] = av.y;
            As[(c4 * 4 + 2) * 68 + r] = av.z;
            As[(c4 * 4 + 3) * 68 + r] = av.w;
            float4 bv = *(const float4*)(W + (size_t)(o0 + r) * IN_FEAT + k0 + c4 * 4);
            Bs[(c4 * 4 + 0) * 68 + r] = bv.x;
            Bs[(c4 * 4 + 1) * 68 + r] = bv.y;
            Bs[(c4 * 4 + 2) * 68 + r] = bv.z;
            Bs[(c4 * 4 + 3) * 68 + r] = bv.w;
        }
        __syncthreads();
#pragma unroll
        for (int kk = 0; kk < 32; kk++) {
            float4 a = *(const float4*)(As + kk * 68 + ty * 4);
            float4 b = *(const float4*)(Bs + kk * 68 + tx * 4);
            float ar[4] = {a.x, a.y, a.z, a.w};
            float br[4] = {b.x, b.y, b.z, b.w};
#pragma unroll
            for (int i = 0; i < 4; i++)
#pragma unroll
                for (int j = 0; j < 4; j++)
                    acc[i][j] = fmaf(ar[i], br[j], acc[i][j]);
        }
        __syncthreads();
    }

#pragma unroll
    for (int i = 0; i < 4; i++) {
        float4 v = make_float4(acc[i][0], acc[i][1], acc[i][2], acc[i][3]);
        *(float4*)(d_g + (size_t)(n0 + ty * 4 + i) * OUT_FEAT + o0 + tx * 4) = v;
    }
}

// ---------------------------------------------------------------------------
// Kernel 2: s_i[n,h] = g[n,h,:] . a[:32] ;  s_j[n,h] = g[n,h,:] . a[32:]
// One thread per (n,h). 32768 threads.
// ---------------------------------------------------------------------------
__global__ __launch_bounds__(256) void score_kernel(const float* __restrict__ a) {
    int gidx = blockIdx.x * blockDim.x + threadIdx.x;  // 0..32767
    int n  = gidx >> 3;
    int hh = gidx & 7;
    const float* grow = d_g + (size_t)n * OUT_FEAT + hh * N_HIDDEN;
    float si = 0.f, sj = 0.f;
#pragma unroll
    for (int f = 0; f < N_HIDDEN; f++) {
        float gv = grow[f];
        si = fmaf(gv, __ldg(a + f), si);
        sj = fmaf(gv, __ldg(a + N_HIDDEN + f), sj);
    }
    d_si[n * N_HEADS + hh] = si;
    d_sj[n * N_HEADS + hh] = sj;
}

// ---------------------------------------------------------------------------
// Kernel 3: flash-style masked attention + P@G via tf32 mma.sync.
// Grid: 128 CTAs, BI=32 i-rows each. Block: 256 threads = 8 warps, warp w = head w.
// Loop j in BJ=64 tiles. Scores built directly in mma A-fragment layout:
//   w = adj ? exp(lrelu(s_i + s_j)) : 0   (no max subtraction needed: |s|<~1)
// Row sums (softmax denominators) accumulated in fp32 before tf32 quantization.
// ---------------------------------------------------------------------------
__device__ __forceinline__ unsigned cvt_tf32(float x) {
    unsigned r;
    asm("cvt.rna.tf32.f32 %0, %1;" : "=r"(r) : "f"(x));
    return r;
}

__global__ __launch_bounds__(256) void attn_kernel(const int* __restrict__ adj,
                                                   float* __restrict__ out) {
    __shared__ float sjS[N_HEADS * 64];            // [h][j_local]
    __shared__ unsigned char adjS[32 * 68];        // [i_local][j_local], stride 68

    const int i0   = blockIdx.x * 32;
    const int tid  = threadIdx.x;
    const int h    = tid >> 5;                     // warp = head
    const int lane = tid & 31;
    const int gid  = lane >> 2;                    // 0..7
    const int tig  = lane & 3;                     // 0..3

    // Preload s_i for the 4 rows this lane touches (rows m*8+gid, m=0..3)
    float si4[4];
#pragma unroll
    for (int m = 0; m < 4; m++)
        si4[m] = d_si[(size_t)(i0 + m * 8 + gid) * N_HEADS + h];

    float acc[2][4][4] = {};       // [mtile][ntile][c0..c3]
    float rs[4] = {0.f, 0.f, 0.f, 0.f};

    const float* gh = d_g + h * N_HIDDEN;

    for (int j0 = 0; j0 < N_NODES; j0 += 64) {
        __syncthreads();
        // stage s_j tile: 512 floats
#pragma unroll
        for (int rep = 0; rep < 2; rep++) {
            int idx = tid + rep * 256;             // 0..511
            int jl = idx >> 3, hh = idx & 7;
            sjS[hh * 64 + jl] = d_sj[(size_t)(j0 + jl) * N_HEADS + hh];
        }
        // stage adjacency tile: 32x64 int32 -> bytes (int4 vectorized)
#pragma unroll
        for (int rep = 0; rep < 2; rep++) {
            int idx = tid + rep * 256;             // 0..511
            int il = idx >> 4, jv = idx & 15;
            int4 v = __ldg((const int4*)(adj + (size_t)(i0 + il) * N_NODES + j0 + jv * 4));
            uchar4 b;
            b.x = (v.x != 0); b.y = (v.y != 0); b.z = (v.z != 0); b.w = (v.w != 0);
            *(uchar4*)(adjS + il * 68 + jv * 4) = b;
        }
        __syncthreads();

#pragma unroll
        for (int kt = 0; kt < 8; kt++) {
            const int jc0 = kt * 8 + tig;          // A cols tig, tig+4
            const int jc1 = jc0 + 4;
            const float sj0 = sjS[h * 64 + jc0];
            const float sj1 = sjS[h * 64 + jc1];

            // B fragments (G tile): row = tig / tig+4 within k-chunk, col = nt*8+gid
            const int jr0 = j0 + kt * 8 + tig;
            const float* gr0 = gh + (size_t)jr0 * OUT_FEAT;
            const float* gr1 = gh + (size_t)(jr0 + 4) * OUT_FEAT;
            unsigned bfr[4][2];
#pragma unroll
            for (int nt = 0; nt < 4; nt++) {
                bfr[nt][0] = cvt_tf32(__ldg(gr0 + nt * 8 + gid));
                bfr[nt][1] = cvt_tf32(__ldg(gr1 + nt * 8 + gid));
            }

#pragma unroll
            for (int mt = 0; mt < 2; mt++) {
                const unsigned char* ar0 = adjS + (mt * 16 + gid) * 68;
                const unsigned char* ar1 = ar0 + 8 * 68;

                float x00 = si4[2 * mt]     + sj0;   // (row gid,   col tig)
                float x01 = si4[2 * mt]     + sj1;   // (row gid,   col tig+4)
                float x10 = si4[2 * mt + 1] + sj0;   // (row gid+8, col tig)
                float x11 = si4[2 * mt + 1] + sj1;   // (row gid+8, col tig+4)

                float w00 = ar0[jc0] ? __expf(fmaxf(x00, 0.2f * x00)) : 0.f;
                float w01 = ar0[jc1] ? __expf(fmaxf(x01, 0.2f * x01)) : 0.f;
                float w10 = ar1[jc0] ? __expf(fmaxf(x10, 0.2f * x10)) : 0.f;
                float w11 = ar1[jc1] ? __expf(fmaxf(x11, 0.2f * x11)) : 0.f;

                rs[2 * mt]     += w00 + w01;
                rs[2 * mt + 1] += w10 + w11;

                unsigned a0 = cvt_tf32(w00);   // A frag: a0(r,c) a1(r+8,c) a2(r,c+4) a3(r+8,c+4)
                unsigned a1 = cvt_tf32(w10);
                unsigned a2 = cvt_tf32(w01);
                unsigned a3 = cvt_tf32(w11);

#pragma unroll
                for (int nt = 0; nt < 4; nt++) {
                    asm volatile(
                        "mma.sync.aligned.m16n8k8.row.col.f32.tf32.tf32.f32 "
                        "{%0,%1,%2,%3}, {%4,%5,%6,%7}, {%8,%9}, {%0,%1,%2,%3};"
                        : "+f"(acc[mt][nt][0]), "+f"(acc[mt][nt][1]),
                          "+f"(acc[mt][nt][2]), "+f"(acc[mt][nt][3])
                        : "r"(a0), "r"(a1), "r"(a2), "r"(a3),
                          "r"(bfr[nt][0]), "r"(bfr[nt][1]));
                }
            }
        }
    }

    // Reduce row sums across the 4 lanes (tig) sharing each row
#pragma unroll
    for (int m = 0; m < 4; m++) {
        rs[m] += __shfl_xor_sync(0xffffffffu, rs[m], 1);
        rs[m] += __shfl_xor_sync(0xffffffffu, rs[m], 2);
    }
    float inv[4];
#pragma unroll
    for (int m = 0; m < 4; m++) inv[m] = 1.0f / rs[m];

    // Write normalized output. C frag: c0(r, 2*tig) c1(r, 2*tig+1) c2(r+8, ..) c3
#pragma unroll
    for (int mt = 0; mt < 2; mt++) {
        int r0 = i0 + mt * 16 + gid;
        int r1 = r0 + 8;
        float in0 = inv[2 * mt], in1 = inv[2 * mt + 1];
#pragma unroll
        for (int nt = 0; nt < 4; nt++) {
            int c = h * N_HIDDEN + nt * 8 + tig * 2;
            float2 v0 = make_float2(acc[mt][nt][0] * in0, acc[mt][nt][1] * in0);
            float2 v1 = make_float2(acc[mt][nt][2] * in1, acc[mt][nt][3] * in1);
            *(float2*)(out + (size_t)r0 * OUT_FEAT + c) = v0;
            *(float2*)(out + (size_t)r1 * OUT_FEAT + c) = v1;
        }
    }
}

// ---------------------------------------------------------------------------
// Launch
// ---------------------------------------------------------------------------
extern "C" void kernel_launch(void* const* d_in, const int* in_sizes, int n_in,
                              void* d_out, int out_size) {
    const float* h   = (const float*)d_in[0];   // [4096, 256]
    const float* W   = (const float*)d_in[1];   // [256, 256]
    const float* a   = (const float*)d_in[2];   // [64]
    const int*   adj = (const int*)d_in[3];     // [4096, 4096, 1]
    float* out = (float*)d_out;                 // [4096, 256]

    (void)in_sizes; (void)n_in; (void)out_size;

    dim3 g1(N_NODES / 64, OUT_FEAT / 64);
    gemm_hW_kernel<<<g1, 256>>>(h, W);

    score_kernel<<<(N_NODES * N_HEADS) / 256, 256>>>(a);

    attn_kernel<<<N_NODES / 32, 256>>>(adj, out);
}

// round 5
// speedup vs baseline: 3.1031x; 3.1031x over previous
#include <cuda_runtime.h>
#include <cstdint>
#include <cstddef>

#define N_NODES 4096
#define IN_FEAT 256
#define N_HEADS 8
#define N_HIDDEN 32
#define OUT_FEAT 256   // N_HEADS * N_HIDDEN
#define JSPLIT 7
#define LOG2E 1.4426950408889634f

// Scratch (static __device__ globals: allocation-free per harness rules)
__device__ float d_g[N_NODES * OUT_FEAT];            // 4 MB: g = h @ W^T
__device__ float d_si[N_NODES * N_HEADS];            // s_i[n][h] * log2(e)
__device__ float d_sj[N_NODES * N_HEADS];            // s_j[n][h] * log2(e)
__device__ unsigned d_gfrag[N_HEADS * 512 * 32 * 8]; // 4 MB: tf32 B-fragments
__device__ float d_part[JSPLIT][N_NODES * OUT_FEAT]; // 28 MB partial outputs
__device__ float d_rs[JSPLIT][N_NODES * N_HEADS];    // partial row sums

__device__ __forceinline__ unsigned cvt_tf32(float x) {
    unsigned r;
    asm("cvt.rna.tf32.f32 %0, %1;" : "=r"(r) : "f"(x));
    return r;
}
__device__ __forceinline__ float ex2(float x) {
    float r;
    asm("ex2.approx.f32 %0, %1;" : "=f"(r) : "f"(x));
    return r;
}
__device__ __forceinline__ void mma_tf32(float* c, unsigned a0, unsigned a1,
                                         unsigned a2, unsigned a3,
                                         unsigned b0, unsigned b1) {
    asm volatile(
        "mma.sync.aligned.m16n8k8.row.col.f32.tf32.tf32.f32 "
        "{%0,%1,%2,%3}, {%4,%5,%6,%7}, {%8,%9}, {%0,%1,%2,%3};"
        : "+f"(c[0]), "+f"(c[1]), "+f"(c[2]), "+f"(c[3])
        : "r"(a0), "r"(a1), "r"(a2), "r"(a3), "r"(b0), "r"(b1));
}

// ---------------------------------------------------------------------------
// Kernel 1: g = h @ W^T   (fp32 tiled GEMM, unchanged from R4)
// ---------------------------------------------------------------------------
__global__ __launch_bounds__(256) void gemm_hW_kernel(const float* __restrict__ h,
                                                      const float* __restrict__ W) {
    __shared__ __align__(16) float As[32 * 68];
    __shared__ __align__(16) float Bs[32 * 68];

    const int n0 = blockIdx.x * 64;
    const int o0 = blockIdx.y * 64;
    const int t  = threadIdx.x;
    const int tx = t & 15;
    const int ty = t >> 4;

    float acc[4][4] = {};

    for (int k0 = 0; k0 < IN_FEAT; k0 += 32) {
#pragma unroll
        for (int rep = 0; rep < 2; rep++) {
            int idx = t + rep * 256;
            int r   = idx >> 3;
            int c4  = idx & 7;
            float4 av = *(const float4*)(h + (size_t)(n0 + r) * IN_FEAT + k0 + c4 * 4);
            As[(c4 * 4 + 0) * 68 + r] = av.x;
            As[(c4 * 4 + 1) * 68 + r] = av.y;
            As[(c4 * 4 + 2) * 68 + r] = av.z;
            As[(c4 * 4 + 3) * 68 + r] = av.w;
            float4 bv = *(const float4*)(W + (size_t)(o0 + r) * IN_FEAT + k0 + c4 * 4);
            Bs[(c4 * 4 + 0) * 68 + r] = bv.x;
            Bs[(c4 * 4 + 1) * 68 + r] = bv.y;
            Bs[(c4 * 4 + 2) * 68 + r] = bv.z;
            Bs[(c4 * 4 + 3) * 68 + r] = bv.w;
        }
        __syncthreads();
#pragma unroll
        for (int kk = 0; kk < 32; kk++) {
            float4 a = *(const float4*)(As + kk * 68 + ty * 4);
            float4 b = *(const float4*)(Bs + kk * 68 + tx * 4);
            float ar[4] = {a.x, a.y, a.z, a.w};
            float br[4] = {b.x, b.y, b.z, b.w};
#pragma unroll
            for (int i = 0; i < 4; i++)
#pragma unroll
                for (int j = 0; j < 4; j++)
                    acc[i][j] = fmaf(ar[i], br[j], acc[i][j]);
        }
        __syncthreads();
    }

#pragma unroll
    for (int i = 0; i < 4; i++) {
        float4 v = make_float4(acc[i][0], acc[i][1], acc[i][2], acc[i][3]);
        *(float4*)(d_g + (size_t)(n0 + ty * 4 + i) * OUT_FEAT + o0 + tx * 4) = v;
    }
}

// ---------------------------------------------------------------------------
// Kernel 2: s_i, s_j (pre-scaled by log2(e) so the inner loop uses raw ex2;
// leaky_relu is positively homogeneous so the scale commutes with it)
// ---------------------------------------------------------------------------
__global__ __launch_bounds__(256) void score_kernel(const float* __restrict__ a) {
    int gidx = blockIdx.x * blockDim.x + threadIdx.x;  // 0..32767
    int n  = gidx >> 3;
    int hh = gidx & 7;
    const float* grow = d_g + (size_t)n * OUT_FEAT + hh * N_HIDDEN;
    float si = 0.f, sj = 0.f;
#pragma unroll
    for (int f = 0; f < N_HIDDEN; f++) {
        float gv = grow[f];
        si = fmaf(gv, __ldg(a + f), si);
        sj = fmaf(gv, __ldg(a + N_HIDDEN + f), sj);
    }
    d_si[n * N_HEADS + hh] = si * LOG2E;
    d_sj[n * N_HEADS + hh] = sj * LOG2E;
}

// ---------------------------------------------------------------------------
// Kernel 3: pack G into mma B-fragment order, pre-converted to tf32 bits.
// Layout: d_gfrag[((h*512 + ktg)*32 + lane)*8 + nt*2 + half]
//   value = tf32( G[ktg*8 + half*4 + tig][h*32 + nt*8 + gid] )
// Inner attention loop then does 2 coalesced LDG.128 per kt.
// ---------------------------------------------------------------------------
__global__ __launch_bounds__(256) void pack_kernel() {
    int gt   = blockIdx.x * 256 + threadIdx.x;   // 0..131071
    int lane = gt & 31;
    int p    = gt >> 5;                          // 0..4095
    int ktg  = p & 511;
    int hh   = p >> 9;
    int gid  = lane >> 2, tig = lane & 3;
    int jb   = ktg * 8;

    unsigned v[8];
#pragma unroll
    for (int nt = 0; nt < 4; nt++)
#pragma unroll
        for (int half = 0; half < 2; half++) {
            float gv = d_g[(size_t)(jb + half * 4 + tig) * OUT_FEAT + hh * N_HIDDEN + nt * 8 + gid];
            v[nt * 2 + half] = cvt_tf32(gv);
        }
    uint4* dst = (uint4*)d_gfrag + (size_t)gt * 2;
    dst[0] = make_uint4(v[0], v[1], v[2], v[3]);
    dst[1] = make_uint4(v[4], v[5], v[6], v[7]);
}

// ---------------------------------------------------------------------------
// Kernel 4: attention. Grid (64 i-tiles of 64 rows, JSPLIT j-stripes) = 448
// CTAs (~3.03 waves on 148 SMs). 512 threads = 16 warps: warp w -> head w&7,
// i-half w>>3 (32 rows). Adjacency as ballot-packed 64-bit register masks;
// B-fragments via 2x LDG.128 per kt; row sums via a ones-column MMA.
// Outputs UNNORMALIZED partial acc + partial row sums.
// ---------------------------------------------------------------------------
__global__ __launch_bounds__(512) void attn_kernel(const int* __restrict__ adj) {
    __shared__ float sjS[N_HEADS * 64];
    __shared__ uint2 adjBits[64];

    const int i0    = blockIdx.x * 64;
    const int js    = blockIdx.y;          // 0..JSPLIT-1
    const int tid   = threadIdx.x;
    const int w     = tid >> 5;
    const int h     = w & 7;
    const int ihalf = w >> 3;
    const int lane  = tid & 31;
    const int gid   = lane >> 2;
    const int tig   = lane & 3;

    float si4[4];
#pragma unroll
    for (int m = 0; m < 4; m++)
        si4[m] = d_si[(size_t)(i0 + ihalf * 32 + m * 8 + gid) * N_HEADS + h];

    float acc[2][4][4] = {};
    float accS[2][4]   = {};
    const unsigned bones = (gid == 0) ? 0x3F800000u : 0u;

    const uint4* fragbase = (const uint4*)d_gfrag + (size_t)h * 512 * 32 * 2;

    for (int jt = js; jt < 64; jt += JSPLIT) {
        const int j0 = jt * 64;
        __syncthreads();
        // stage s_j tile (coalesced)
        {
            int jl = tid >> 3, hh = tid & 7;
            sjS[hh * 64 + jl] = d_sj[(size_t)(j0 + jl) * N_HEADS + hh];
        }
        // adjacency -> 64-bit masks via ballot (warp w stages rows 4w..4w+3)
#pragma unroll
        for (int rr = 0; rr < 4; rr++) {
            int r = w * 4 + rr;
            const int* arow = adj + (size_t)(i0 + r) * N_NODES + j0;
            unsigned b0 = __ballot_sync(0xffffffffu, arow[lane] != 0);
            unsigned b1 = __ballot_sync(0xffffffffu, arow[32 + lane] != 0);
            if (lane == 0) adjBits[r] = make_uint2(b0, b1);
        }
        __syncthreads();

        uint2 msk[4];
#pragma unroll
        for (int m = 0; m < 4; m++)
            msk[m] = adjBits[ihalf * 32 + m * 8 + gid];

#pragma unroll
        for (int kt = 0; kt < 8; kt++) {
            const uint4* fb = fragbase + ((size_t)(jt * 8 + kt) * 32 + lane) * 2;
            uint4 q0 = __ldg(fb);
            uint4 q1 = __ldg(fb + 1);
            float sj0 = sjS[h * 64 + kt * 8 + tig];
            float sj1 = sjS[h * 64 + kt * 8 + tig + 4];
            const unsigned sh = (kt & 3) * 8 + tig;

#pragma unroll
            for (int mt = 0; mt < 2; mt++) {
                unsigned w0 = (kt < 4) ? msk[2 * mt].x     : msk[2 * mt].y;
                unsigned w1 = (kt < 4) ? msk[2 * mt + 1].x : msk[2 * mt + 1].y;
                unsigned t0 = w0 >> sh;
                unsigned t1 = w1 >> sh;

                float x00 = si4[2 * mt] + sj0;
                float x01 = si4[2 * mt] + sj1;
                float x10 = si4[2 * mt + 1] + sj0;
                float x11 = si4[2 * mt + 1] + sj1;

                float e00 = ex2(fmaxf(x00, 0.2f * x00));
                float e01 = ex2(fmaxf(x01, 0.2f * x01));
                float e10 = ex2(fmaxf(x10, 0.2f * x10));
                float e11 = ex2(fmaxf(x11, 0.2f * x11));

                // round-to-nearest tf32 (add half-ulp into ignored bits), masked
                unsigned a0 = (t0 & 1u)  ? __float_as_uint(e00) + 0x1000u : 0u;
                unsigned a2 = (t0 & 16u) ? __float_as_uint(e01) + 0x1000u : 0u;
                unsigned a1 = (t1 & 1u)  ? __float_as_uint(e10) + 0x1000u : 0u;
                unsigned a3 = (t1 & 16u) ? __float_as_uint(e11) + 0x1000u : 0u;

                mma_tf32(acc[mt][0], a0, a1, a2, a3, q0.x, q0.y);
                mma_tf32(acc[mt][1], a0, a1, a2, a3, q0.z, q0.w);
                mma_tf32(acc[mt][2], a0, a1, a2, a3, q1.x, q1.y);
                mma_tf32(acc[mt][3], a0, a1, a2, a3, q1.z, q1.w);
                mma_tf32(accS[mt],   a0, a1, a2, a3, bones, bones);
            }
        }
    }

    const int rbase = i0 + ihalf * 32;
    // partial row sums: tig==0 lanes hold col-0 of the ones-MMA (c0: row gid, c2: row gid+8)
    if (tig == 0) {
        d_rs[js][(size_t)(rbase + gid) * N_HEADS + h]      = accS[0][0];
        d_rs[js][(size_t)(rbase + 8 + gid) * N_HEADS + h]  = accS[0][2];
        d_rs[js][(size_t)(rbase + 16 + gid) * N_HEADS + h] = accS[1][0];
        d_rs[js][(size_t)(rbase + 24 + gid) * N_HEADS + h] = accS[1][2];
    }
    // partial (unnormalized) output
#pragma unroll
    for (int mt = 0; mt < 2; mt++) {
        int r0 = rbase + mt * 16 + gid;
        int r1 = r0 + 8;
#pragma unroll
        for (int nt = 0; nt < 4; nt++) {
            int c = h * N_HIDDEN + nt * 8 + tig * 2;
            *(float2*)(&d_part[js][(size_t)r0 * OUT_FEAT + c]) =
                make_float2(acc[mt][nt][0], acc[mt][nt][1]);
            *(float2*)(&d_part[js][(size_t)r1 * OUT_FEAT + c]) =
                make_float2(acc[mt][nt][2], acc[mt][nt][3]);
        }
    }
}

// ---------------------------------------------------------------------------
// Kernel 5: reduce partials and normalize.
// ---------------------------------------------------------------------------
__global__ __launch_bounds__(256) void reduce_kernel(float* __restrict__ out) {
    int t  = blockIdx.x * 256 + threadIdx.x;   // 0..262143
    int i  = t >> 6;
    int c4 = t & 63;
    int hh = c4 >> 3;

    float4 num = make_float4(0.f, 0.f, 0.f, 0.f);
    float den = 0.f;
#pragma unroll
    for (int s = 0; s < JSPLIT; s++) {
        float4 p = *(const float4*)(&d_part[s][(size_t)i * OUT_FEAT + c4 * 4]);
        num.x += p.x; num.y += p.y; num.z += p.z; num.w += p.w;
        den += d_rs[s][(size_t)i * N_HEADS + hh];
    }
    float inv = 1.0f / den;
    *(float4*)(out + (size_t)i * OUT_FEAT + c4 * 4) =
        make_float4(num.x * inv, num.y * inv, num.z * inv, num.w * inv);
}

// ---------------------------------------------------------------------------
// Launch
// ---------------------------------------------------------------------------
extern "C" void kernel_launch(void* const* d_in, const int* in_sizes, int n_in,
                              void* d_out, int out_size) {
    const float* h   = (const float*)d_in[0];   // [4096, 256]
    const float* W   = (const float*)d_in[1];   // [256, 256]
    const float* a   = (const float*)d_in[2];   // [64]
    const int*   adj = (const int*)d_in[3];     // [4096, 4096, 1]
    float* out = (float*)d_out;                 // [4096, 256]

    (void)in_sizes; (void)n_in; (void)out_size;

    dim3 g1(N_NODES / 64, OUT_FEAT / 64);
    gemm_hW_kernel<<<g1, 256>>>(h, W);

    score_kernel<<<(N_NODES * N_HEADS) / 256, 256>>>(a);
    pack_kernel<<<512, 256>>>();

    attn_kernel<<<dim3(N_NODES / 64, JSPLIT), 512>>>(adj);

    reduce_kernel<<<(N_NODES * OUT_FEAT / 4) / 256, 256>>>(out);
}

// round 10
// speedup vs baseline: 3.1930x; 1.0290x over previous
#include <cuda_runtime.h>
#include <cstdint>
#include <cstddef>

#define N_NODES 4096
#define IN_FEAT 256
#define N_HEADS 8
#define N_HIDDEN 32
#define OUT_FEAT 256   // N_HEADS * N_HIDDEN
#define JSPLIT 7
#define LOG2E 1.4426950408889634f

// Scratch (static __device__ globals: allocation-free per harness rules)
__device__ float d_g[N_NODES * OUT_FEAT];            // 4 MB: g = h @ W^T
__device__ float d_si[N_NODES * N_HEADS];            // s_i[n][h] * log2(e)
__device__ float d_sj[N_NODES * N_HEADS];            // s_j[n][h] * log2(e)
__device__ unsigned d_gfrag[N_HEADS * 512 * 32 * 8]; // 4 MB: tf32 B-fragments
__device__ float d_part[JSPLIT][N_NODES * OUT_FEAT]; // 28 MB partial outputs
__device__ float d_rs[JSPLIT][N_NODES * N_HEADS];    // partial row sums

__device__ __forceinline__ unsigned cvt_tf32(float x) {
    unsigned r;
    asm("cvt.rna.tf32.f32 %0, %1;" : "=r"(r) : "f"(x));
    return r;
}
__device__ __forceinline__ float ex2(float x) {
    float r;
    asm("ex2.approx.f32 %0, %1;" : "=f"(r) : "f"(x));
    return r;
}
__device__ __forceinline__ void mma_tf32(float* c, unsigned a0, unsigned a1,
                                         unsigned a2, unsigned a3,
                                         unsigned b0, unsigned b1) {
    asm volatile(
        "mma.sync.aligned.m16n8k8.row.col.f32.tf32.tf32.f32 "
        "{%0,%1,%2,%3}, {%4,%5,%6,%7}, {%8,%9}, {%0,%1,%2,%3};"
        : "+f"(c[0]), "+f"(c[1]), "+f"(c[2]), "+f"(c[3])
        : "r"(a0), "r"(a1), "r"(a2), "r"(a3), "r"(b0), "r"(b1));
}

// ---------------------------------------------------------------------------
// Kernel 1: g = h @ W^T   (fp32 tiled GEMM)
// BM=64, BN=32, BK=32 -> grid (64,8) = 512 CTAs for better wave fill.
// 256 threads, 2x4 microtile per thread.
// ---------------------------------------------------------------------------
__global__ __launch_bounds__(256) void gemm_hW_kernel(const float* __restrict__ h,
                                                      const float* __restrict__ W) {
    __shared__ __align__(16) float As[32 * 68];  // [kk][row 0..63], stride 68
    __shared__ __align__(16) float Bs[32 * 36];  // [kk][col 0..31], stride 36

    const int n0 = blockIdx.x * 64;
    const int o0 = blockIdx.y * 32;
    const int t  = threadIdx.x;
    const int tx = t & 7;        // 8 col-groups of 4
    const int ty = t >> 3;       // 32 row-groups of 2

    float acc[2][4] = {};

    for (int k0 = 0; k0 < IN_FEAT; k0 += 32) {
#pragma unroll
        for (int rep = 0; rep < 2; rep++) {
            int idx = t + rep * 256;          // 0..511
            int r   = idx >> 3;               // 0..63
            int c4  = idx & 7;
            float4 av = *(const float4*)(h + (size_t)(n0 + r) * IN_FEAT + k0 + c4 * 4);
            As[(c4 * 4 + 0) * 68 + r] = av.x;
            As[(c4 * 4 + 1) * 68 + r] = av.y;
            As[(c4 * 4 + 2) * 68 + r] = av.z;
            As[(c4 * 4 + 3) * 68 + r] = av.w;
        }
        {
            int r  = t >> 3;                  // 0..31
            int c4 = t & 7;
            float4 bv = *(const float4*)(W + (size_t)(o0 + r) * IN_FEAT + k0 + c4 * 4);
            Bs[(c4 * 4 + 0) * 36 + r] = bv.x;
            Bs[(c4 * 4 + 1) * 36 + r] = bv.y;
            Bs[(c4 * 4 + 2) * 36 + r] = bv.z;
            Bs[(c4 * 4 + 3) * 36 + r] = bv.w;
        }
        __syncthreads();
#pragma unroll
        for (int kk = 0; kk < 32; kk++) {
            float2 a = *(const float2*)(As + kk * 68 + ty * 2);
            float4 b = *(const float4*)(Bs + kk * 36 + tx * 4);
            float ar[2] = {a.x, a.y};
            float br[4] = {b.x, b.y, b.z, b.w};
#pragma unroll
            for (int i = 0; i < 2; i++)
#pragma unroll
                for (int j = 0; j < 4; j++)
                    acc[i][j] = fmaf(ar[i], br[j], acc[i][j]);
        }
        __syncthreads();
    }

#pragma unroll
    for (int i = 0; i < 2; i++) {
        float4 v = make_float4(acc[i][0], acc[i][1], acc[i][2], acc[i][3]);
        *(float4*)(d_g + (size_t)(n0 + ty * 2 + i) * OUT_FEAT + o0 + tx * 4) = v;
    }
}

// ---------------------------------------------------------------------------
// Kernel 2: s_i, s_j (pre-scaled by log2(e); lrelu is positively homogeneous
// so the scale commutes, inner loop uses raw ex2)
// ---------------------------------------------------------------------------
__global__ __launch_bounds__(256) void score_kernel(const float* __restrict__ a) {
    int gidx = blockIdx.x * blockDim.x + threadIdx.x;  // 0..32767
    int n  = gidx >> 3;
    int hh = gidx & 7;
    const float* grow = d_g + (size_t)n * OUT_FEAT + hh * N_HIDDEN;
    float si = 0.f, sj = 0.f;
#pragma unroll
    for (int f = 0; f < N_HIDDEN; f++) {
        float gv = grow[f];
        si = fmaf(gv, __ldg(a + f), si);
        sj = fmaf(gv, __ldg(a + N_HIDDEN + f), sj);
    }
    d_si[n * N_HEADS + hh] = si * LOG2E;
    d_sj[n * N_HEADS + hh] = sj * LOG2E;
}

// ---------------------------------------------------------------------------
// Kernel 3: pack G into mma B-fragment order, pre-converted (rounded) tf32.
// Layout: d_gfrag[((h*512 + ktg)*32 + lane)*8 + nt*2 + half]
//   value = tf32( G[ktg*8 + half*4 + tig][h*32 + nt*8 + gid] )
// ---------------------------------------------------------------------------
__global__ __launch_bounds__(256) void pack_kernel() {
    int gt   = blockIdx.x * 256 + threadIdx.x;   // 0..131071
    int lane = gt & 31;
    int p    = gt >> 5;                          // 0..4095
    int ktg  = p & 511;
    int hh   = p >> 9;
    int gid  = lane >> 2, tig = lane & 3;
    int jb   = ktg * 8;

    unsigned v[8];
#pragma unroll
    for (int nt = 0; nt < 4; nt++)
#pragma unroll
        for (int half = 0; half < 2; half++) {
            float gv = d_g[(size_t)(jb + half * 4 + tig) * OUT_FEAT + hh * N_HIDDEN + nt * 8 + gid];
            v[nt * 2 + half] = cvt_tf32(gv);
        }
    uint4* dst = (uint4*)d_gfrag + (size_t)gt * 2;
    dst[0] = make_uint4(v[0], v[1], v[2], v[3]);
    dst[1] = make_uint4(v[4], v[5], v[6], v[7]);
}

// ---------------------------------------------------------------------------
// Kernel 4: attention. Grid (128 i-tiles of 32 rows, JSPLIT j-stripes) = 896
// CTAs. 256 threads = 8 warps, warp w = head w, 32 rows each (mt=2).
// launch_bounds(256,3): reg cap 85 -> 3 CTAs/SM -> 6 warps/SMSP.
// Masks read per-kt from smem (broadcast LDS) instead of living in regs.
// A fragments: truncated tf32 (no rounding) — denominators use the SAME
// quantized weights (ones-column MMA), so the ratio is an exact softmax over
// the quantized weights; quantization acts as a tiny weight perturbation.
// Outputs UNNORMALIZED partial acc + partial row sums.
// ---------------------------------------------------------------------------
__global__ __launch_bounds__(256, 3) void attn_kernel(const int* __restrict__ adj) {
    __shared__ float sjS[N_HEADS * 64];
    __shared__ unsigned adjLo[32];   // bits j0..j0+31 for 32 i-rows
    __shared__ unsigned adjHi[32];   // bits j0+32..j0+63

    const int i0   = blockIdx.x * 32;
    const int js   = blockIdx.y;           // 0..JSPLIT-1
    const int tid  = threadIdx.x;
    const int w    = tid >> 5;             // warp = head
    const int h    = w;
    const int lane = tid & 31;
    const int gid  = lane >> 2;
    const int tig  = lane & 3;

    float si4[4];
#pragma unroll
    for (int m = 0; m < 4; m++)
        si4[m] = d_si[(size_t)(i0 + m * 8 + gid) * N_HEADS + h];

    float acc[2][4][4] = {};
    float accS[2][4]   = {};
    const unsigned bones = (gid == 0) ? 0x3F800000u : 0u;

    const uint4* fragbase = (const uint4*)d_gfrag + (size_t)h * 512 * 32 * 2;

    for (int jt = js; jt < 64; jt += JSPLIT) {
        const int j0 = jt * 64;
        __syncthreads();
        // stage s_j tile (512 floats, 2 reps)
#pragma unroll
        for (int rep = 0; rep < 2; rep++) {
            int idx = tid + rep * 256;
            int jl = idx >> 3, hh = idx & 7;
            sjS[hh * 64 + jl] = d_sj[(size_t)(j0 + jl) * N_HEADS + hh];
        }
        // adjacency -> bitmasks via ballot (warp w stages rows 4w..4w+3)
#pragma unroll
        for (int rr = 0; rr < 4; rr++) {
            int r = w * 4 + rr;
            const int* arow = adj + (size_t)(i0 + r) * N_NODES + j0;
            unsigned b0 = __ballot_sync(0xffffffffu, arow[lane] != 0);
            unsigned b1 = __ballot_sync(0xffffffffu, arow[32 + lane] != 0);
            if (lane == 0) { adjLo[r] = b0; adjHi[r] = b1; }
        }
        __syncthreads();

#pragma unroll
        for (int kt = 0; kt < 8; kt++) {
            const uint4* fb = fragbase + ((size_t)(jt * 8 + kt) * 32 + lane) * 2;
            uint4 q0 = __ldg(fb);
            uint4 q1 = __ldg(fb + 1);
            float sj0 = sjS[h * 64 + kt * 8 + tig];
            float sj1 = sjS[h * 64 + kt * 8 + tig + 4];
            const unsigned* adjHalf = (kt < 4) ? adjLo : adjHi;  // compile-time
            const int sh = (kt & 3) * 8 + tig;                   // one reg per kt

#pragma unroll
            for (int mt = 0; mt < 2; mt++) {
                unsigned t0 = adjHalf[mt * 16 + gid]     >> sh;
                unsigned t1 = adjHalf[mt * 16 + 8 + gid] >> sh;

                float x00 = si4[2 * mt] + sj0;
                float x01 = si4[2 * mt] + sj1;
                float x10 = si4[2 * mt + 1] + sj0;
                float x11 = si4[2 * mt + 1] + sj1;

                float e00 = ex2(fmaxf(x00, 0.2f * x00));
                float e01 = ex2(fmaxf(x01, 0.2f * x01));
                float e10 = ex2(fmaxf(x10, 0.2f * x10));
                float e11 = ex2(fmaxf(x11, 0.2f * x11));

                unsigned a0 = (t0 & 1u)  ? __float_as_uint(e00) : 0u;
                unsigned a2 = (t0 & 16u) ? __float_as_uint(e01) : 0u;
                unsigned a1 = (t1 & 1u)  ? __float_as_uint(e10) : 0u;
                unsigned a3 = (t1 & 16u) ? __float_as_uint(e11) : 0u;

                mma_tf32(acc[mt][0], a0, a1, a2, a3, q0.x, q0.y);
                mma_tf32(acc[mt][1], a0, a1, a2, a3, q0.z, q0.w);
                mma_tf32(acc[mt][2], a0, a1, a2, a3, q1.x, q1.y);
                mma_tf32(acc[mt][3], a0, a1, a2, a3, q1.z, q1.w);
                mma_tf32(accS[mt],   a0, a1, a2, a3, bones, bones);
            }
        }
    }

    // partial row sums: tig==0 lanes hold col 0 of the ones-MMA
    if (tig == 0) {
        d_rs[js][(size_t)(i0 + gid) * N_HEADS + h]      = accS[0][0];
        d_rs[js][(size_t)(i0 + 8 + gid) * N_HEADS + h]  = accS[0][2];
        d_rs[js][(size_t)(i0 + 16 + gid) * N_HEADS + h] = accS[1][0];
        d_rs[js][(size_t)(i0 + 24 + gid) * N_HEADS + h] = accS[1][2];
    }
    // partial (unnormalized) output
#pragma unroll
    for (int mt = 0; mt < 2; mt++) {
        int r0 = i0 + mt * 16 + gid;
        int r1 = r0 + 8;
#pragma unroll
        for (int nt = 0; nt < 4; nt++) {
            int c = h * N_HIDDEN + nt * 8 + tig * 2;
            *(float2*)(&d_part[js][(size_t)r0 * OUT_FEAT + c]) =
                make_float2(acc[mt][nt][0], acc[mt][nt][1]);
            *(float2*)(&d_part[js][(size_t)r1 * OUT_FEAT + c]) =
                make_float2(acc[mt][nt][2], acc[mt][nt][3]);
        }
    }
}

// ---------------------------------------------------------------------------
// Kernel 5: reduce partials and normalize.
// ---------------------------------------------------------------------------
__global__ __launch_bounds__(256) void reduce_kernel(float* __restrict__ out) {
    int t  = blockIdx.x * 256 + threadIdx.x;   // 0..262143
    int i  = t >> 6;
    int c4 = t & 63;
    int hh = c4 >> 3;

    float4 num = make_float4(0.f, 0.f, 0.f, 0.f);
    float den = 0.f;
#pragma unroll
    for (int s = 0; s < JSPLIT; s++) {
        float4 p = *(const float4*)(&d_part[s][(size_t)i * OUT_FEAT + c4 * 4]);
        num.x += p.x; num.y += p.y; num.z += p.z; num.w += p.w;
        den += d_rs[s][(size_t)i * N_HEADS + hh];
    }
    float inv = 1.0f / den;
    *(float4*)(out + (size_t)i * OUT_FEAT + c4 * 4) =
        make_float4(num.x * inv, num.y * inv, num.z * inv, num.w * inv);
}

// ---------------------------------------------------------------------------
// Launch
// ---------------------------------------------------------------------------
extern "C" void kernel_launch(void* const* d_in, const int* in_sizes, int n_in,
                              void* d_out, int out_size) {
    const float* h   = (const float*)d_in[0];   // [4096, 256]
    const float* W   = (const float*)d_in[1];   // [256, 256]
    const float* a   = (const float*)d_in[2];   // [64]
    const int*   adj = (const int*)d_in[3];     // [4096, 4096, 1]
    float* out = (float*)d_out;                 // [4096, 256]

    (void)in_sizes; (void)n_in; (void)out_size;

    dim3 g1(N_NODES / 64, OUT_FEAT / 32);
    gemm_hW_kernel<<<g1, 256>>>(h, W);

    score_kernel<<<(N_NODES * N_HEADS) / 256, 256>>>(a);
    pack_kernel<<<512, 256>>>();

    attn_kernel<<<dim3(N_NODES / 32, JSPLIT), 256>>>(adj);

    reduce_kernel<<<(N_NODES * OUT_FEAT / 4) / 256, 256>>>(out);
}

// round 12
// speedup vs baseline: 3.2581x; 1.0204x over previous
#include <cuda_runtime.h>
#include <cstdint>
#include <cstddef>

#define N_NODES 4096
#define IN_FEAT 256
#define N_HEADS 8
#define N_HIDDEN 32
#define OUT_FEAT 256   // N_HEADS * N_HIDDEN
#define JSPLIT 7
#define LOG2E 1.4426950408889634f

// Scratch (static __device__ globals: allocation-free per harness rules)
__device__ float d_si[N_NODES * N_HEADS];            // s_i[n][h] * log2(e)
__device__ float d_sj[N_NODES * N_HEADS];            // s_j[n][h] * log2(e)
__device__ unsigned d_gfrag[N_HEADS * 512 * 32 * 8]; // 4 MB: tf32 B-fragments
__device__ float d_part[JSPLIT][N_NODES * OUT_FEAT]; // 28 MB partial outputs
__device__ float d_rs[JSPLIT][N_NODES * N_HEADS];    // partial row sums

__device__ __forceinline__ unsigned cvt_tf32(float x) {
    unsigned r;
    asm("cvt.rna.tf32.f32 %0, %1;" : "=r"(r) : "f"(x));
    return r;
}
__device__ __forceinline__ float ex2(float x) {
    float r;
    asm("ex2.approx.f32 %0, %1;" : "=f"(r) : "f"(x));
    return r;
}
__device__ __forceinline__ void mma_tf32(float* c, unsigned a0, unsigned a1,
                                         unsigned a2, unsigned a3,
                                         unsigned b0, unsigned b1) {
    asm volatile(
        "mma.sync.aligned.m16n8k8.row.col.f32.tf32.tf32.f32 "
        "{%0,%1,%2,%3}, {%4,%5,%6,%7}, {%8,%9}, {%0,%1,%2,%3};"
        : "+f"(c[0]), "+f"(c[1]), "+f"(c[2]), "+f"(c[3])
        : "r"(a0), "r"(a1), "r"(a2), "r"(a3), "r"(b0), "r"(b1));
}

// ---------------------------------------------------------------------------
// Kernel 1 (fused): g = h @ W^T for one (64-row, 1-head) tile, THEN
//   - s_i/s_j for those rows via in-register dot + shfl reduce
//   - tf32 B-fragment pack straight to d_gfrag (g never hits gmem)
// BM=64, BN=32(=one head), BK=32 -> grid (64, 8) = 512 CTAs, 256 threads.
// ---------------------------------------------------------------------------
__global__ __launch_bounds__(256) void gemm_fused_kernel(const float* __restrict__ h,
                                                         const float* __restrict__ W,
                                                         const float* __restrict__ a) {
    __shared__ __align__(16) float As[32 * 68];  // mainloop: [kk][row], stride 68
    __shared__ __align__(16) float Bs[32 * 36];  // mainloop: [kk][col], stride 36

    const int n0 = blockIdx.x * 64;
    const int hb = blockIdx.y;               // head 0..7
    const int o0 = hb * 32;
    const int t  = threadIdx.x;
    const int tx = t & 7;        // 8 col-groups of 4 (covers the 32-wide head)
    const int ty = t >> 3;       // 32 row-groups of 2

    float acc[2][4] = {};

    for (int k0 = 0; k0 < IN_FEAT; k0 += 32) {
#pragma unroll
        for (int rep = 0; rep < 2; rep++) {
            int idx = t + rep * 256;          // 0..511
            int r   = idx >> 3;               // 0..63
            int c4  = idx & 7;
            float4 av = *(const float4*)(h + (size_t)(n0 + r) * IN_FEAT + k0 + c4 * 4);
            As[(c4 * 4 + 0) * 68 + r] = av.x;
            As[(c4 * 4 + 1) * 68 + r] = av.y;
            As[(c4 * 4 + 2) * 68 + r] = av.z;
            As[(c4 * 4 + 3) * 68 + r] = av.w;
        }
        {
            int r  = t >> 3;                  // 0..31
            int c4 = t & 7;
            float4 bv = *(const float4*)(W + (size_t)(o0 + r) * IN_FEAT + k0 + c4 * 4);
            Bs[(c4 * 4 + 0) * 36 + r] = bv.x;
            Bs[(c4 * 4 + 1) * 36 + r] = bv.y;
            Bs[(c4 * 4 + 2) * 36 + r] = bv.z;
            Bs[(c4 * 4 + 3) * 36 + r] = bv.w;
        }
        __syncthreads();
#pragma unroll
        for (int kk = 0; kk < 32; kk++) {
            float2 av = *(const float2*)(As + kk * 68 + ty * 2);
            float4 bv = *(const float4*)(Bs + kk * 36 + tx * 4);
            float ar[2] = {av.x, av.y};
            float br[4] = {bv.x, bv.y, bv.z, bv.w};
#pragma unroll
            for (int i = 0; i < 2; i++)
#pragma unroll
                for (int j = 0; j < 4; j++)
                    acc[i][j] = fmaf(ar[i], br[j], acc[i][j]);
        }
        __syncthreads();
    }

    // --- epilogue A: s_i / s_j for the 2 rows this thread owns ---
    {
        float ps[4] = {0.f, 0.f, 0.f, 0.f};   // si0, sj0, si1, sj1
#pragma unroll
        for (int j = 0; j < 4; j++) {
            float alv = __ldg(a + tx * 4 + j);
            float arv = __ldg(a + 32 + tx * 4 + j);
            ps[0] = fmaf(acc[0][j], alv, ps[0]);
            ps[1] = fmaf(acc[0][j], arv, ps[1]);
            ps[2] = fmaf(acc[1][j], alv, ps[2]);
            ps[3] = fmaf(acc[1][j], arv, ps[3]);
        }
        // reduce over tx (lanes with same ty are 8 consecutive lanes)
#pragma unroll
        for (int off = 1; off < 8; off <<= 1)
#pragma unroll
            for (int q = 0; q < 4; q++)
                ps[q] += __shfl_xor_sync(0xffffffffu, ps[q], off);
        if (tx == 0) {
            d_si[(size_t)(n0 + ty * 2 + 0) * N_HEADS + hb] = ps[0] * LOG2E;
            d_sj[(size_t)(n0 + ty * 2 + 0) * N_HEADS + hb] = ps[1] * LOG2E;
            d_si[(size_t)(n0 + ty * 2 + 1) * N_HEADS + hb] = ps[2] * LOG2E;
            d_sj[(size_t)(n0 + ty * 2 + 1) * N_HEADS + hb] = ps[3] * LOG2E;
        }
    }

    // --- epilogue B: stage g tile to smem, pack tf32 fragments ---
    __syncthreads();                 // done with As/Bs
    float* gS = As;                  // reuse as [64][33] (2112 <= 2176 floats)
#pragma unroll
    for (int i = 0; i < 2; i++)
#pragma unroll
        for (int j = 0; j < 4; j++)
            gS[(ty * 2 + i) * 33 + tx * 4 + j] = acc[i][j];
    __syncthreads();

    {
        int ktg  = t >> 5;           // 0..7 local fragment group
        int lane = t & 31;
        int gid  = lane >> 2, tig = lane & 3;
        unsigned v[8];
#pragma unroll
        for (int nt = 0; nt < 4; nt++)
#pragma unroll
            for (int half = 0; half < 2; half++)
                v[nt * 2 + half] =
                    cvt_tf32(gS[(ktg * 8 + half * 4 + tig) * 33 + nt * 8 + gid]);
        size_t gt = ((size_t)hb * 512 + (n0 >> 3) + ktg) * 32 + lane;
        uint4* dst = (uint4*)d_gfrag + gt * 2;
        dst[0] = make_uint4(v[0], v[1], v[2], v[3]);
        dst[1] = make_uint4(v[4], v[5], v[6], v[7]);
    }
}

// ---------------------------------------------------------------------------
// Kernel 2: attention. Grid (128 i-tiles of 32 rows, JSPLIT stripes) = 896
// CTAs, 256 threads = 8 warps (warp = head), launch_bounds(256,3).
// KEY: exp(lrelu(si+sj)) == max(Ei*Ej, Fi*Fj) with E=2^s', F=2^{0.2 s'}
// (s' already scaled by log2 e), because 2^x >= 2^{0.2x} iff x >= 0.
// -> zero MUFU in the hot loop, chain is FMUL->FMNMX->SEL->MMA.
// Masks: ballot-packed bits, held in 4 regs, reloaded at kt==0 / kt==4.
// Numerator and ones-MMA denominator use identical tf32-truncated weights,
// so the softmax ratio is exact over the quantized weights.
// ---------------------------------------------------------------------------
__global__ __launch_bounds__(256, 3) void attn_kernel(const int* __restrict__ adj) {
    __shared__ float2 efS[N_HEADS * 64];   // (Ej, Fj) per [h][j_local]
    __shared__ unsigned adjLo[32];         // bits j0..j0+31 for 32 i-rows
    __shared__ unsigned adjHi[32];         // bits j0+32..j0+63

    const int i0   = blockIdx.x * 32;
    const int js   = blockIdx.y;           // 0..JSPLIT-1
    const int tid  = threadIdx.x;
    const int w    = tid >> 5;             // warp = head
    const int h    = w;
    const int lane = tid & 31;
    const int gid  = lane >> 2;
    const int tig  = lane & 3;

    float Ei[4], Fi[4];
#pragma unroll
    for (int m = 0; m < 4; m++) {
        float s = d_si[(size_t)(i0 + m * 8 + gid) * N_HEADS + h];
        Ei[m] = ex2(s);
        Fi[m] = ex2(0.2f * s);
    }

    float acc[2][4][4] = {};
    float accS[2][4]   = {};
    const unsigned bones = (gid == 0) ? 0x3F800000u : 0u;

    const uint4* fragbase = (const uint4*)d_gfrag + (size_t)h * 512 * 32 * 2;

    for (int jt = js; jt < 64; jt += JSPLIT) {
        const int j0 = jt * 64;
        __syncthreads();
        // stage (Ej, Fj) tile: 512 pairs, 2 reps, coalesced d_sj read
#pragma unroll
        for (int rep = 0; rep < 2; rep++) {
            int idx = tid + rep * 256;
            int jl = idx >> 3, hh = idx & 7;
            float sj = d_sj[(size_t)(j0 + jl) * N_HEADS + hh];
            efS[hh * 64 + jl] = make_float2(ex2(sj), ex2(0.2f * sj));
        }
        // adjacency -> bitmasks via ballot (warp w stages rows 4w..4w+3)
#pragma unroll
        for (int rr = 0; rr < 4; rr++) {
            int r = w * 4 + rr;
            const int* arow = adj + (size_t)(i0 + r) * N_NODES + j0;
            unsigned b0 = __ballot_sync(0xffffffffu, arow[lane] != 0);
            unsigned b1 = __ballot_sync(0xffffffffu, arow[32 + lane] != 0);
            if (lane == 0) { adjLo[r] = b0; adjHi[r] = b1; }
        }
        __syncthreads();

        unsigned mrow[4];
#pragma unroll
        for (int kt = 0; kt < 8; kt++) {
            if (kt == 0) {
                mrow[0] = adjLo[gid];      mrow[1] = adjLo[8 + gid];
                mrow[2] = adjLo[16 + gid]; mrow[3] = adjLo[24 + gid];
            }
            if (kt == 4) {
                mrow[0] = adjHi[gid];      mrow[1] = adjHi[8 + gid];
                mrow[2] = adjHi[16 + gid]; mrow[3] = adjHi[24 + gid];
            }
            const uint4* fb = fragbase + ((size_t)(jt * 8 + kt) * 32 + lane) * 2;
            uint4 q0 = __ldg(fb);
            uint4 q1 = __ldg(fb + 1);
            float2 ef0 = efS[h * 64 + kt * 8 + tig];
            float2 ef1 = efS[h * 64 + kt * 8 + tig + 4];
            const int sh = (kt & 3) * 8 + tig;

#pragma unroll
            for (int mt = 0; mt < 2; mt++) {
                unsigned t0 = mrow[2 * mt]     >> sh;
                unsigned t1 = mrow[2 * mt + 1] >> sh;

                float w00 = fmaxf(Ei[2 * mt]     * ef0.x, Fi[2 * mt]     * ef0.y);
                float w01 = fmaxf(Ei[2 * mt]     * ef1.x, Fi[2 * mt]     * ef1.y);
                float w10 = fmaxf(Ei[2 * mt + 1] * ef0.x, Fi[2 * mt + 1] * ef0.y);
                float w11 = fmaxf(Ei[2 * mt + 1] * ef1.x, Fi[2 * mt + 1] * ef1.y);

                unsigned a0 = (t0 & 1u)  ? __float_as_uint(w00) : 0u;
                unsigned a2 = (t0 & 16u) ? __float_as_uint(w01) : 0u;
                unsigned a1 = (t1 & 1u)  ? __float_as_uint(w10) : 0u;
                unsigned a3 = (t1 & 16u) ? __float_as_uint(w11) : 0u;

                mma_tf32(acc[mt][0], a0, a1, a2, a3, q0.x, q0.y);
                mma_tf32(acc[mt][1], a0, a1, a2, a3, q0.z, q0.w);
                mma_tf32(acc[mt][2], a0, a1, a2, a3, q1.x, q1.y);
                mma_tf32(acc[mt][3], a0, a1, a2, a3, q1.z, q1.w);
                mma_tf32(accS[mt],   a0, a1, a2, a3, bones, bones);
            }
        }
    }

    // partial row sums: tig==0 lanes hold col 0 of the ones-MMA
    if (tig == 0) {
        d_rs[js][(size_t)(i0 + gid) * N_HEADS + h]      = accS[0][0];
        d_rs[js][(size_t)(i0 + 8 + gid) * N_HEADS + h]  = accS[0][2];
        d_rs[js][(size_t)(i0 + 16 + gid) * N_HEADS + h] = accS[1][0];
        d_rs[js][(size_t)(i0 + 24 + gid) * N_HEADS + h] = accS[1][2];
    }
    // partial (unnormalized) output
#pragma unroll
    for (int mt = 0; mt < 2; mt++) {
        int r0 = i0 + mt * 16 + gid;
        int r1 = r0 + 8;
#pragma unroll
        for (int nt = 0; nt < 4; nt++) {
            int c = h * N_HIDDEN + nt * 8 + tig * 2;
            *(float2*)(&d_part[js][(size_t)r0 * OUT_FEAT + c]) =
                make_float2(acc[mt][nt][0], acc[mt][nt][1]);
            *(float2*)(&d_part[js][(size_t)r1 * OUT_FEAT + c]) =
                make_float2(acc[mt][nt][2], acc[mt][nt][3]);
        }
    }
}

// ---------------------------------------------------------------------------
// Kernel 3: reduce partials and normalize.
// ---------------------------------------------------------------------------
__global__ __launch_bounds__(256) void reduce_kernel(float* __restrict__ out) {
    int t  = blockIdx.x * 256 + threadIdx.x;   // 0..262143
    int i  = t >> 6;
    int c4 = t & 63;
    int hh = c4 >> 3;

    float4 num = make_float4(0.f, 0.f, 0.f, 0.f);
    float den = 0.f;
#pragma unroll
    for (int s = 0; s < JSPLIT; s++) {
        float4 p = *(const float4*)(&d_part[s][(size_t)i * OUT_FEAT + c4 * 4]);
        num.x += p.x; num.y += p.y; num.z += p.z; num.w += p.w;
        den += d_rs[s][(size_t)i * N_HEADS + hh];
    }
    float inv = 1.0f / den;
    *(float4*)(out + (size_t)i * OUT_FEAT + c4 * 4) =
        make_float4(num.x * inv, num.y * inv, num.z * inv, num.w * inv);
}

// ---------------------------------------------------------------------------
// Launch
// ---------------------------------------------------------------------------
extern "C" void kernel_launch(void* const* d_in, const int* in_sizes, int n_in,
                              void* d_out, int out_size) {
    const float* h   = (const float*)d_in[0];   // [4096, 256]
    const float* W   = (const float*)d_in[1];   // [256, 256]
    const float* a   = (const float*)d_in[2];   // [64]
    const int*   adj = (const int*)d_in[3];     // [4096, 4096, 1]
    float* out = (float*)d_out;                 // [4096, 256]

    (void)in_sizes; (void)n_in; (void)out_size;

    dim3 g1(N_NODES / 64, N_HEADS);
    gemm_fused_kernel<<<g1, 256>>>(h, W, a);

    attn_kernel<<<dim3(N_NODES / 32, JSPLIT), 256>>>(adj);

    reduce_kernel<<<(N_NODES * OUT_FEAT / 4) / 256, 256>>>(out);
}

// round 13
// speedup vs baseline: 3.8354x; 1.1772x over previous
#include <cuda_runtime.h>
#include <cstdint>
#include <cstddef>

#define N_NODES 4096
#define IN_FEAT 256
#define N_HEADS 8
#define N_HIDDEN 32
#define OUT_FEAT 256   // N_HEADS * N_HIDDEN
#define JSPLIT 7
#define LOG2E 1.4426950408889634f

// Scratch (static __device__ globals: allocation-free per harness rules)
__device__ float d_si[N_NODES * N_HEADS];            // s_i[n][h] * log2(e)
__device__ float d_sj[N_NODES * N_HEADS];            // s_j[n][h] * log2(e)
__device__ unsigned d_gfrag[N_HEADS * 512 * 32 * 8]; // 4 MB: tf32 B-fragments
__device__ float d_part[JSPLIT][N_NODES * OUT_FEAT]; // 28 MB partial outputs
__device__ float d_rs[JSPLIT][N_NODES * N_HEADS];    // partial row sums

__device__ __forceinline__ unsigned cvt_tf32(float x) {
    unsigned r;
    asm("cvt.rna.tf32.f32 %0, %1;" : "=r"(r) : "f"(x));
    return r;
}
__device__ __forceinline__ float ex2(float x) {
    float r;
    asm("ex2.approx.f32 %0, %1;" : "=f"(r) : "f"(x));
    return r;
}
__device__ __forceinline__ void mma_tf32(float* c, unsigned a0, unsigned a1,
                                         unsigned a2, unsigned a3,
                                         unsigned b0, unsigned b1) {
    asm volatile(
        "mma.sync.aligned.m16n8k8.row.col.f32.tf32.tf32.f32 "
        "{%0,%1,%2,%3}, {%4,%5,%6,%7}, {%8,%9}, {%0,%1,%2,%3};"
        : "+f"(c[0]), "+f"(c[1]), "+f"(c[2]), "+f"(c[3])
        : "r"(a0), "r"(a1), "r"(a2), "r"(a3), "r"(b0), "r"(b1));
}

// ---------------------------------------------------------------------------
// Kernel 1 (fused): g = h @ W^T for one (64-row, 2-head) tile using the R4
// BM=64/BN=64/BK=32 mainloop (4x4 microtile, measured 24us), THEN
//   - s_i/s_j for those rows via in-register dot + 8-lane shfl reduce
//   - tf32 B-fragment pack for BOTH heads straight to d_gfrag
// grid (64, 4) = 256 CTAs, 256 threads. g never touches gmem.
// ---------------------------------------------------------------------------
__global__ __launch_bounds__(256) void gemm_fused_kernel(const float* __restrict__ h,
                                                         const float* __restrict__ W,
                                                         const float* __restrict__ a) {
    __shared__ __align__(16) float buf[4352];    // As(2176) + Bs(2176); reused as gS(4224)
    float* As = buf;            // mainloop: [kk][row], stride 68
    float* Bs = buf + 2176;     // mainloop: [kk][col], stride 68

    const int n0 = blockIdx.x * 64;
    const int by = blockIdx.y;               // head pair: heads 2by, 2by+1
    const int o0 = by * 64;
    const int t  = threadIdx.x;
    const int tx = t & 15;       // 16 col-groups of 4
    const int ty = t >> 4;       // 16 row-groups of 4

    float acc[4][4] = {};

    for (int k0 = 0; k0 < IN_FEAT; k0 += 32) {
#pragma unroll
        for (int rep = 0; rep < 2; rep++) {
            int idx = t + rep * 256;          // 0..511
            int r   = idx >> 3;               // 0..63
            int c4  = idx & 7;
            float4 av = *(const float4*)(h + (size_t)(n0 + r) * IN_FEAT + k0 + c4 * 4);
            As[(c4 * 4 + 0) * 68 + r] = av.x;
            As[(c4 * 4 + 1) * 68 + r] = av.y;
            As[(c4 * 4 + 2) * 68 + r] = av.z;
            As[(c4 * 4 + 3) * 68 + r] = av.w;
            float4 bv = *(const float4*)(W + (size_t)(o0 + r) * IN_FEAT + k0 + c4 * 4);
            Bs[(c4 * 4 + 0) * 68 + r] = bv.x;
            Bs[(c4 * 4 + 1) * 68 + r] = bv.y;
            Bs[(c4 * 4 + 2) * 68 + r] = bv.z;
            Bs[(c4 * 4 + 3) * 68 + r] = bv.w;
        }
        __syncthreads();
#pragma unroll
        for (int kk = 0; kk < 32; kk++) {
            float4 av = *(const float4*)(As + kk * 68 + ty * 4);
            float4 bv = *(const float4*)(Bs + kk * 68 + tx * 4);
            float ar[4] = {av.x, av.y, av.z, av.w};
            float br[4] = {bv.x, bv.y, bv.z, bv.w};
#pragma unroll
            for (int i = 0; i < 4; i++)
#pragma unroll
                for (int j = 0; j < 4; j++)
                    acc[i][j] = fmaf(ar[i], br[j], acc[i][j]);
        }
        __syncthreads();
    }

    // --- epilogue A: s_i / s_j for the 4 rows this thread owns ---
    // cols tx*4..tx*4+3; tx<8 -> head 2by, tx>=8 -> head 2by+1.
    {
        const int hc = tx & 7;               // col-group within the head
        float ps[8] = {};                    // (si,sj) x 4 rows
#pragma unroll
        for (int j = 0; j < 4; j++) {
            float alv = __ldg(a + hc * 4 + j);
            float arv = __ldg(a + 32 + hc * 4 + j);
#pragma unroll
            for (int i = 0; i < 4; i++) {
                ps[2 * i]     = fmaf(acc[i][j], alv, ps[2 * i]);
                ps[2 * i + 1] = fmaf(acc[i][j], arv, ps[2 * i + 1]);
            }
        }
        // reduce over the 8 lanes sharing (ty, tx-half): xor offsets 1,2,4
        // stay inside the half (bit 3 of lane untouched).
#pragma unroll
        for (int off = 1; off < 8; off <<= 1)
#pragma unroll
            for (int q = 0; q < 8; q++)
                ps[q] += __shfl_xor_sync(0xffffffffu, ps[q], off);
        if ((tx & 7) == 0) {
            int head = 2 * by + (tx >> 3);
#pragma unroll
            for (int i = 0; i < 4; i++) {
                d_si[(size_t)(n0 + ty * 4 + i) * N_HEADS + head] = ps[2 * i] * LOG2E;
                d_sj[(size_t)(n0 + ty * 4 + i) * N_HEADS + head] = ps[2 * i + 1] * LOG2E;
            }
        }
    }

    // --- epilogue B: stage g tile to smem, pack tf32 fragments (2 heads) ---
    __syncthreads();                 // done with As/Bs
    float* gS = buf;                 // [64][66] = 4224 <= 4352 floats
#pragma unroll
    for (int i = 0; i < 4; i++)
#pragma unroll
        for (int j = 0; j < 4; j++)
            gS[(ty * 4 + i) * 66 + tx * 4 + j] = acc[i][j];
    __syncthreads();

#pragma unroll
    for (int rep = 0; rep < 2; rep++) {
        int grp  = (t >> 5) + rep * 8;   // 0..15: hd = grp>>3, ktg = grp&7
        int hd   = grp >> 3;
        int ktg  = grp & 7;
        int lane = t & 31;
        int gid  = lane >> 2, tig = lane & 3;
        unsigned v[8];
#pragma unroll
        for (int nt = 0; nt < 4; nt++)
#pragma unroll
            for (int half = 0; half < 2; half++)
                v[nt * 2 + half] = cvt_tf32(
                    gS[(ktg * 8 + half * 4 + tig) * 66 + hd * 32 + nt * 8 + gid]);
        size_t gt = ((size_t)(2 * by + hd) * 512 + (n0 >> 3) + ktg) * 32 + lane;
        uint4* dst = (uint4*)d_gfrag + gt * 2;
        dst[0] = make_uint4(v[0], v[1], v[2], v[3]);
        dst[1] = make_uint4(v[4], v[5], v[6], v[7]);
    }
}

// ---------------------------------------------------------------------------
// Kernel 2: attention. Grid (128 i-tiles of 32 rows, JSPLIT stripes) = 896
// CTAs, 256 threads = 8 warps (warp = head), launch_bounds(256,3).
// exp(lrelu(si+sj)) == max(Ei*Ej, Fi*Fj), E=2^s', F=2^{0.2 s'} -> no MUFU
// in the hot loop. Row sums now via FADD of the masked, EXPLICITLY
// tf32-truncated weights (AND 0xFFFFE000) instead of a ones-column MMA:
// tensor work drops 20% and the FADD denominator sees exactly the values
// the MMA numerator sees, keeping the softmax ratio exact over quantized
// weights. Masks: ballot-packed bits in 4 regs, reloaded at kt==0/4.
// ---------------------------------------------------------------------------
__global__ __launch_bounds__(256, 3) void attn_kernel(const int* __restrict__ adj) {
    __shared__ float2 efS[N_HEADS * 64];   // (Ej, Fj) per [h][j_local]
    __shared__ unsigned adjLo[32];         // bits j0..j0+31 for 32 i-rows
    __shared__ unsigned adjHi[32];         // bits j0+32..j0+63

    const int i0   = blockIdx.x * 32;
    const int js   = blockIdx.y;           // 0..JSPLIT-1
    const int tid  = threadIdx.x;
    const int w    = tid >> 5;             // warp = head
    const int h    = w;
    const int lane = tid & 31;
    const int gid  = lane >> 2;
    const int tig  = lane & 3;

    float Ei[4], Fi[4];
#pragma unroll
    for (int m = 0; m < 4; m++) {
        float s = d_si[(size_t)(i0 + m * 8 + gid) * N_HEADS + h];
        Ei[m] = ex2(s);
        Fi[m] = ex2(0.2f * s);
    }

    float acc[2][4][4] = {};
    float rs[4] = {0.f, 0.f, 0.f, 0.f};

    const uint4* fragbase = (const uint4*)d_gfrag + (size_t)h * 512 * 32 * 2;

    for (int jt = js; jt < 64; jt += JSPLIT) {
        const int j0 = jt * 64;
        __syncthreads();
        // stage (Ej, Fj) tile: 512 pairs, 2 reps, coalesced d_sj read
#pragma unroll
        for (int rep = 0; rep < 2; rep++) {
            int idx = tid + rep * 256;
            int jl = idx >> 3, hh = idx & 7;
            float sj = d_sj[(size_t)(j0 + jl) * N_HEADS + hh];
            efS[hh * 64 + jl] = make_float2(ex2(sj), ex2(0.2f * sj));
        }
        // adjacency -> bitmasks via ballot (warp w stages rows 4w..4w+3)
#pragma unroll
        for (int rr = 0; rr < 4; rr++) {
            int r = w * 4 + rr;
            const int* arow = adj + (size_t)(i0 + r) * N_NODES + j0;
            unsigned b0 = __ballot_sync(0xffffffffu, arow[lane] != 0);
            unsigned b1 = __ballot_sync(0xffffffffu, arow[32 + lane] != 0);
            if (lane == 0) { adjLo[r] = b0; adjHi[r] = b1; }
        }
        __syncthreads();

        unsigned mrow[4];
#pragma unroll
        for (int kt = 0; kt < 8; kt++) {
            if (kt == 0) {
                mrow[0] = adjLo[gid];      mrow[1] = adjLo[8 + gid];
                mrow[2] = adjLo[16 + gid]; mrow[3] = adjLo[24 + gid];
            }
            if (kt == 4) {
                mrow[0] = adjHi[gid];      mrow[1] = adjHi[8 + gid];
                mrow[2] = adjHi[16 + gid]; mrow[3] = adjHi[24 + gid];
            }
            const uint4* fb = fragbase + ((size_t)(jt * 8 + kt) * 32 + lane) * 2;
            uint4 q0 = __ldg(fb);
            uint4 q1 = __ldg(fb + 1);
            float2 ef0 = efS[h * 64 + kt * 8 + tig];
            float2 ef1 = efS[h * 64 + kt * 8 + tig + 4];
            const int sh = (kt & 3) * 8 + tig;

#pragma unroll
            for (int mt = 0; mt < 2; mt++) {
                unsigned t0 = mrow[2 * mt]     >> sh;
                unsigned t1 = mrow[2 * mt + 1] >> sh;

                float w00 = fmaxf(Ei[2 * mt]     * ef0.x, Fi[2 * mt]     * ef0.y);
                float w01 = fmaxf(Ei[2 * mt]     * ef1.x, Fi[2 * mt]     * ef1.y);
                float w10 = fmaxf(Ei[2 * mt + 1] * ef0.x, Fi[2 * mt + 1] * ef0.y);
                float w11 = fmaxf(Ei[2 * mt + 1] * ef1.x, Fi[2 * mt + 1] * ef1.y);

                // masked + explicitly tf32-truncated (matches HW MMA operand view)
                unsigned a0 = (t0 & 1u)  ? (__float_as_uint(w00) & 0xFFFFE000u) : 0u;
                unsigned a2 = (t0 & 16u) ? (__float_as_uint(w01) & 0xFFFFE000u) : 0u;
                unsigned a1 = (t1 & 1u)  ? (__float_as_uint(w10) & 0xFFFFE000u) : 0u;
                unsigned a3 = (t1 & 16u) ? (__float_as_uint(w11) & 0xFFFFE000u) : 0u;

                rs[2 * mt]     += __uint_as_float(a0) + __uint_as_float(a2);
                rs[2 * mt + 1] += __uint_as_float(a1) + __uint_as_float(a3);

                mma_tf32(acc[mt][0], a0, a1, a2, a3, q0.x, q0.y);
                mma_tf32(acc[mt][1], a0, a1, a2, a3, q0.z, q0.w);
                mma_tf32(acc[mt][2], a0, a1, a2, a3, q1.x, q1.y);
                mma_tf32(acc[mt][3], a0, a1, a2, a3, q1.z, q1.w);
            }
        }
    }

    // reduce row sums across the 4 tig lanes sharing each row
#pragma unroll
    for (int m = 0; m < 4; m++) {
        rs[m] += __shfl_xor_sync(0xffffffffu, rs[m], 1);
        rs[m] += __shfl_xor_sync(0xffffffffu, rs[m], 2);
    }
    if (tig == 0) {
#pragma unroll
        for (int m = 0; m < 4; m++)
            d_rs[js][(size_t)(i0 + m * 8 + gid) * N_HEADS + h] = rs[m];
    }
    // partial (unnormalized) output
#pragma unroll
    for (int mt = 0; mt < 2; mt++) {
        int r0 = i0 + mt * 16 + gid;
        int r1 = r0 + 8;
#pragma unroll
        for (int nt = 0; nt < 4; nt++) {
            int c = h * N_HIDDEN + nt * 8 + tig * 2;
            *(float2*)(&d_part[js][(size_t)r0 * OUT_FEAT + c]) =
                make_float2(acc[mt][nt][0], acc[mt][nt][1]);
            *(float2*)(&d_part[js][(size_t)r1 * OUT_FEAT + c]) =
                make_float2(acc[mt][nt][2], acc[mt][nt][3]);
        }
    }
}

// ---------------------------------------------------------------------------
// Kernel 3: reduce partials and normalize.
// ---------------------------------------------------------------------------
__global__ __launch_bounds__(256) void reduce_kernel(float* __restrict__ out) {
    int t  = blockIdx.x * 256 + threadIdx.x;   // 0..262143
    int i  = t >> 6;
    int c4 = t & 63;
    int hh = c4 >> 3;

    float4 num = make_float4(0.f, 0.f, 0.f, 0.f);
    float den = 0.f;
#pragma unroll
    for (int s = 0; s < JSPLIT; s++) {
        float4 p = *(const float4*)(&d_part[s][(size_t)i * OUT_FEAT + c4 * 4]);
        num.x += p.x; num.y += p.y; num.z += p.z; num.w += p.w;
        den += d_rs[s][(size_t)i * N_HEADS + hh];
    }
    float inv = 1.0f / den;
    *(float4*)(out + (size_t)i * OUT_FEAT + c4 * 4) =
        make_float4(num.x * inv, num.y * inv, num.z * inv, num.w * inv);
}

// ---------------------------------------------------------------------------
// Launch
// ---------------------------------------------------------------------------
extern "C" void kernel_launch(void* const* d_in, const int* in_sizes, int n_in,
                              void* d_out, int out_size) {
    const float* h   = (const float*)d_in[0];   // [4096, 256]
    const float* W   = (const float*)d_in[1];   // [256, 256]
    const float* a   = (const float*)d_in[2];   // [64]
    const int*   adj = (const int*)d_in[3];     // [4096, 4096, 1]
    float* out = (float*)d_out;                 // [4096, 256]

    (void)in_sizes; (void)n_in; (void)out_size;

    dim3 g1(N_NODES / 64, N_HEADS / 2);
    gemm_fused_kernel<<<g1, 256>>>(h, W, a);

    attn_kernel<<<dim3(N_NODES / 32, JSPLIT), 256>>>(adj);

    reduce_kernel<<<(N_NODES * OUT_FEAT / 4) / 256, 256>>>(out);
}

// round 14
// speedup vs baseline: 4.0558x; 1.0574x over previous
#include <cuda_runtime.h>
#include <cstdint>
#include <cstddef>

#define N_NODES 4096
#define IN_FEAT 256
#define N_HEADS 8
#define N_HIDDEN 32
#define OUT_FEAT 256   // N_HEADS * N_HIDDEN
#define JSPLIT 7
#define LOG2E 1.4426950408889634f

// Scratch (static __device__ globals: allocation-free per harness rules)
__device__ float d_si[N_NODES * N_HEADS];            // s_i[n][h] * log2(e)
__device__ float d_sj[N_NODES * N_HEADS];            // s_j[n][h] * log2(e)
__device__ unsigned d_gfrag[N_HEADS * 512 * 32 * 8]; // 4 MB: tf32 B-fragments
__device__ float d_part[JSPLIT][N_NODES * OUT_FEAT]; // 28 MB partial outputs
__device__ float d_rs[JSPLIT][N_NODES * N_HEADS];    // partial row sums

__device__ __forceinline__ unsigned cvt_tf32(float x) {
    unsigned r;
    asm("cvt.rna.tf32.f32 %0, %1;" : "=r"(r) : "f"(x));
    return r;
}
__device__ __forceinline__ float ex2(float x) {
    float r;
    asm("ex2.approx.f32 %0, %1;" : "=f"(r) : "f"(x));
    return r;
}
__device__ __forceinline__ void mma_tf32(float* c, unsigned a0, unsigned a1,
                                         unsigned a2, unsigned a3,
                                         unsigned b0, unsigned b1) {
    asm volatile(
        "mma.sync.aligned.m16n8k8.row.col.f32.tf32.tf32.f32 "
        "{%0,%1,%2,%3}, {%4,%5,%6,%7}, {%8,%9}, {%0,%1,%2,%3};"
        : "+f"(c[0]), "+f"(c[1]), "+f"(c[2]), "+f"(c[3])
        : "r"(a0), "r"(a1), "r"(a2), "r"(a3), "r"(b0), "r"(b1));
}

// ---------------------------------------------------------------------------
// Kernel 1 (fused, NOW TENSOR-CORE): g = h @ W^T for one (64-row, 2-head)
// tile via tf32 mma.m16n8k8, then fused epilogues:
//   A) s_i/s_j from fp32 C-fragments in registers + tig-shfl reduce
//   B) tf32 B-fragment pack for both heads straight to d_gfrag
// grid (64, 4) = 256 CTAs, 256 threads = 8 warps.
// Warp w: rows wr*16..wr*16+15 (wr = w>>1), head col-block wc = w&1.
// Smem stride 36 for A/B (fragment LDS conflict-free: (4*gid+tig)%32 distinct),
// stride 72 for the g re-stage (pack LDS conflict-free: (8*tig+gid)%32).
// Staging converts fp32 -> tf32 with cvt.rna (unbiased) during STS.
// ---------------------------------------------------------------------------
__global__ __launch_bounds__(256) void gemm_fused_kernel(const float* __restrict__ h,
                                                         const float* __restrict__ W,
                                                         const float* __restrict__ a) {
    __shared__ __align__(16) float buf[4608];    // As(64*36) + Bs(64*36); reused as gS(64*72)
    float* As = buf;            // [64][36] tf32 bits of h tile rows
    float* Bs = buf + 2304;     // [64][36] tf32 bits of W tile rows

    const int n0 = blockIdx.x * 64;
    const int by = blockIdx.y;               // head pair: heads 2by, 2by+1
    const int o0 = by * 64;
    const int t  = threadIdx.x;
    const int w  = t >> 5;
    const int lane = t & 31;
    const int wr = w >> 1;       // 16-row block 0..3
    const int wc = w & 1;        // 32-col block (head within pair)
    const int gid = lane >> 2, tig = lane & 3;

    float acc[4][4] = {};        // [nt][c0..c3], C frag: c0(gid,2tig) c1(gid,2tig+1) c2(+8,..) c3

    for (int k0 = 0; k0 < IN_FEAT; k0 += 32) {
        __syncthreads();
#pragma unroll
        for (int rep = 0; rep < 2; rep++) {
            int idx = t + rep * 256;          // 0..511
            int r   = idx >> 3;               // 0..63
            int c4  = idx & 7;
            float4 av = *(const float4*)(h + (size_t)(n0 + r) * IN_FEAT + k0 + c4 * 4);
            uint4 ua;
            ua.x = cvt_tf32(av.x); ua.y = cvt_tf32(av.y);
            ua.z = cvt_tf32(av.z); ua.w = cvt_tf32(av.w);
            *(uint4*)(As + r * 36 + c4 * 4) = ua;
            float4 bv = *(const float4*)(W + (size_t)(o0 + r) * IN_FEAT + k0 + c4 * 4);
            uint4 ub;
            ub.x = cvt_tf32(bv.x); ub.y = cvt_tf32(bv.y);
            ub.z = cvt_tf32(bv.z); ub.w = cvt_tf32(bv.w);
            *(uint4*)(Bs + r * 36 + c4 * 4) = ub;
        }
        __syncthreads();

        const unsigned* Au = (const unsigned*)As;
        const unsigned* Bu = (const unsigned*)Bs;
        const int arow0 = (wr * 16 + gid) * 36;
        const int arow1 = arow0 + 8 * 36;
        const int brow  = (wc * 32 + gid) * 36;
#pragma unroll
        for (int ks = 0; ks < 4; ks++) {
            const int kk = ks * 8 + tig;
            unsigned a0 = Au[arow0 + kk];
            unsigned a1 = Au[arow1 + kk];
            unsigned a2 = Au[arow0 + kk + 4];
            unsigned a3 = Au[arow1 + kk + 4];
#pragma unroll
            for (int nt = 0; nt < 4; nt++) {
                unsigned b0 = Bu[brow + nt * 8 * 36 + kk];
                unsigned b1 = Bu[brow + nt * 8 * 36 + kk + 4];
                mma_tf32(acc[nt], a0, a1, a2, a3, b0, b1);
            }
        }
    }

    // --- epilogue A: s_i/s_j from C fragments (warp covers one head) ---
    {
        float ps[4] = {0.f, 0.f, 0.f, 0.f};   // si_r0, sj_r0, si_r1, sj_r1
#pragma unroll
        for (int nt = 0; nt < 4; nt++) {
            int c0 = nt * 8 + 2 * tig;
            float al0 = __ldg(a + c0),      al1 = __ldg(a + c0 + 1);
            float ar0 = __ldg(a + 32 + c0), ar1 = __ldg(a + 32 + c0 + 1);
            ps[0] += acc[nt][0] * al0 + acc[nt][1] * al1;
            ps[1] += acc[nt][0] * ar0 + acc[nt][1] * ar1;
            ps[2] += acc[nt][2] * al0 + acc[nt][3] * al1;
            ps[3] += acc[nt][2] * ar0 + acc[nt][3] * ar1;
        }
#pragma unroll
        for (int off = 1; off < 4; off <<= 1)
#pragma unroll
            for (int q = 0; q < 4; q++)
                ps[q] += __shfl_xor_sync(0xffffffffu, ps[q], off);
        if (tig == 0) {
            int head = 2 * by + wc;
            int r0 = n0 + wr * 16 + gid;
            d_si[(size_t)r0 * N_HEADS + head]       = ps[0] * LOG2E;
            d_sj[(size_t)r0 * N_HEADS + head]       = ps[1] * LOG2E;
            d_si[(size_t)(r0 + 8) * N_HEADS + head] = ps[2] * LOG2E;
            d_sj[(size_t)(r0 + 8) * N_HEADS + head] = ps[3] * LOG2E;
        }
    }

    // --- epilogue B: re-stage g to smem (stride 72), pack tf32 fragments ---
    __syncthreads();                 // done with As/Bs
    float* gS = buf;                 // [64][72] = 4608 floats exactly
#pragma unroll
    for (int nt = 0; nt < 4; nt++) {
        int col = wc * 32 + nt * 8 + 2 * tig;
        int r0  = wr * 16 + gid;
        *(float2*)(gS + r0 * 72 + col)       = make_float2(acc[nt][0], acc[nt][1]);
        *(float2*)(gS + (r0 + 8) * 72 + col) = make_float2(acc[nt][2], acc[nt][3]);
    }
    __syncthreads();

#pragma unroll
    for (int rep = 0; rep < 2; rep++) {
        int grp = (t >> 5) + rep * 8;    // 0..15: hd = grp>>3, ktg = grp&7
        int hd  = grp >> 3;
        int ktg = grp & 7;
        unsigned v[8];
#pragma unroll
        for (int nt = 0; nt < 4; nt++)
#pragma unroll
            for (int half = 0; half < 2; half++)
                v[nt * 2 + half] = cvt_tf32(
                    gS[(ktg * 8 + half * 4 + tig) * 72 + hd * 32 + nt * 8 + gid]);
        size_t gt = ((size_t)(2 * by + hd) * 512 + (n0 >> 3) + ktg) * 32 + lane;
        uint4* dst = (uint4*)d_gfrag + gt * 2;
        dst[0] = make_uint4(v[0], v[1], v[2], v[3]);
        dst[1] = make_uint4(v[4], v[5], v[6], v[7]);
    }
}

// ---------------------------------------------------------------------------
// Kernel 2: attention (UNCHANGED from R13). Grid (128, JSPLIT) = 896 CTAs,
// 256 threads = 8 warps (warp = head), launch_bounds(256,3).
// exp(lrelu(si+sj)) == max(Ei*Ej, Fi*Fj) -> no MUFU in hot loop.
// Row sums via FADD of masked, explicitly tf32-truncated weights.
// ---------------------------------------------------------------------------
__global__ __launch_bounds__(256, 3) void attn_kernel(const int* __restrict__ adj) {
    __shared__ float2 efS[N_HEADS * 64];   // (Ej, Fj) per [h][j_local]
    __shared__ unsigned adjLo[32];         // bits j0..j0+31 for 32 i-rows
    __shared__ unsigned adjHi[32];         // bits j0+32..j0+63

    const int i0   = blockIdx.x * 32;
    const int js   = blockIdx.y;           // 0..JSPLIT-1
    const int tid  = threadIdx.x;
    const int w    = tid >> 5;             // warp = head
    const int h    = w;
    const int lane = tid & 31;
    const int gid  = lane >> 2;
    const int tig  = lane & 3;

    float Ei[4], Fi[4];
#pragma unroll
    for (int m = 0; m < 4; m++) {
        float s = d_si[(size_t)(i0 + m * 8 + gid) * N_HEADS + h];
        Ei[m] = ex2(s);
        Fi[m] = ex2(0.2f * s);
    }

    float acc[2][4][4] = {};
    float rs[4] = {0.f, 0.f, 0.f, 0.f};

    const uint4* fragbase = (const uint4*)d_gfrag + (size_t)h * 512 * 32 * 2;

    for (int jt = js; jt < 64; jt += JSPLIT) {
        const int j0 = jt * 64;
        __syncthreads();
#pragma unroll
        for (int rep = 0; rep < 2; rep++) {
            int idx = tid + rep * 256;
            int jl = idx >> 3, hh = idx & 7;
            float sj = d_sj[(size_t)(j0 + jl) * N_HEADS + hh];
            efS[hh * 64 + jl] = make_float2(ex2(sj), ex2(0.2f * sj));
        }
#pragma unroll
        for (int rr = 0; rr < 4; rr++) {
            int r = w * 4 + rr;
            const int* arow = adj + (size_t)(i0 + r) * N_NODES + j0;
            unsigned b0 = __ballot_sync(0xffffffffu, arow[lane] != 0);
            unsigned b1 = __ballot_sync(0xffffffffu, arow[32 + lane] != 0);
            if (lane == 0) { adjLo[r] = b0; adjHi[r] = b1; }
        }
        __syncthreads();

        unsigned mrow[4];
#pragma unroll
        for (int kt = 0; kt < 8; kt++) {
            if (kt == 0) {
                mrow[0] = adjLo[gid];      mrow[1] = adjLo[8 + gid];
                mrow[2] = adjLo[16 + gid]; mrow[3] = adjLo[24 + gid];
            }
            if (kt == 4) {
                mrow[0] = adjHi[gid];      mrow[1] = adjHi[8 + gid];
                mrow[2] = adjHi[16 + gid]; mrow[3] = adjHi[24 + gid];
            }
            const uint4* fb = fragbase + ((size_t)(jt * 8 + kt) * 32 + lane) * 2;
            uint4 q0 = __ldg(fb);
            uint4 q1 = __ldg(fb + 1);
            float2 ef0 = efS[h * 64 + kt * 8 + tig];
            float2 ef1 = efS[h * 64 + kt * 8 + tig + 4];
            const int sh = (kt & 3) * 8 + tig;

#pragma unroll
            for (int mt = 0; mt < 2; mt++) {
                unsigned t0 = mrow[2 * mt]     >> sh;
                unsigned t1 = mrow[2 * mt + 1] >> sh;

                float w00 = fmaxf(Ei[2 * mt]     * ef0.x, Fi[2 * mt]     * ef0.y);
                float w01 = fmaxf(Ei[2 * mt]     * ef1.x, Fi[2 * mt]     * ef1.y);
                float w10 = fmaxf(Ei[2 * mt + 1] * ef0.x, Fi[2 * mt + 1] * ef0.y);
                float w11 = fmaxf(Ei[2 * mt + 1] * ef1.x, Fi[2 * mt + 1] * ef1.y);

                unsigned a0 = (t0 & 1u)  ? (__float_as_uint(w00) & 0xFFFFE000u) : 0u;
                unsigned a2 = (t0 & 16u) ? (__float_as_uint(w01) & 0xFFFFE000u) : 0u;
                unsigned a1 = (t1 & 1u)  ? (__float_as_uint(w10) & 0xFFFFE000u) : 0u;
                unsigned a3 = (t1 & 16u) ? (__float_as_uint(w11) & 0xFFFFE000u) : 0u;

                rs[2 * mt]     += __uint_as_float(a0) + __uint_as_float(a2);
                rs[2 * mt + 1] += __uint_as_float(a1) + __uint_as_float(a3);

                mma_tf32(acc[mt][0], a0, a1, a2, a3, q0.x, q0.y);
                mma_tf32(acc[mt][1], a0, a1, a2, a3, q0.z, q0.w);
                mma_tf32(acc[mt][2], a0, a1, a2, a3, q1.x, q1.y);
                mma_tf32(acc[mt][3], a0, a1, a2, a3, q1.z, q1.w);
            }
        }
    }

#pragma unroll
    for (int m = 0; m < 4; m++) {
        rs[m] += __shfl_xor_sync(0xffffffffu, rs[m], 1);
        rs[m] += __shfl_xor_sync(0xffffffffu, rs[m], 2);
    }
    if (tig == 0) {
#pragma unroll
        for (int m = 0; m < 4; m++)
            d_rs[js][(size_t)(i0 + m * 8 + gid) * N_HEADS + h] = rs[m];
    }
#pragma unroll
    for (int mt = 0; mt < 2; mt++) {
        int r0 = i0 + mt * 16 + gid;
        int r1 = r0 + 8;
#pragma unroll
        for (int nt = 0; nt < 4; nt++) {
            int c = h * N_HIDDEN + nt * 8 + tig * 2;
            *(float2*)(&d_part[js][(size_t)r0 * OUT_FEAT + c]) =
                make_float2(acc[mt][nt][0], acc[mt][nt][1]);
            *(float2*)(&d_part[js][(size_t)r1 * OUT_FEAT + c]) =
                make_float2(acc[mt][nt][2], acc[mt][nt][3]);
        }
    }
}

// ---------------------------------------------------------------------------
// Kernel 3: reduce partials and normalize (unchanged).
// ---------------------------------------------------------------------------
__global__ __launch_bounds__(256) void reduce_kernel(float* __restrict__ out) {
    int t  = blockIdx.x * 256 + threadIdx.x;   // 0..262143
    int i  = t >> 6;
    int c4 = t & 63;
    int hh = c4 >> 3;

    float4 num = make_float4(0.f, 0.f, 0.f, 0.f);
    float den = 0.f;
#pragma unroll
    for (int s = 0; s < JSPLIT; s++) {
        float4 p = *(const float4*)(&d_part[s][(size_t)i * OUT_FEAT + c4 * 4]);
        num.x += p.x; num.y += p.y; num.z += p.z; num.w += p.w;
        den += d_rs[s][(size_t)i * N_HEADS + hh];
    }
    float inv = 1.0f / den;
    *(float4*)(out + (size_t)i * OUT_FEAT + c4 * 4) =
        make_float4(num.x * inv, num.y * inv, num.z * inv, num.w * inv);
}

// ---------------------------------------------------------------------------
// Launch
// ---------------------------------------------------------------------------
extern "C" void kernel_launch(void* const* d_in, const int* in_sizes, int n_in,
                              void* d_out, int out_size) {
    const float* h   = (const float*)d_in[0];   // [4096, 256]
    const float* W   = (const float*)d_in[1];   // [256, 256]
    const float* a   = (const float*)d_in[2];   // [64]
    const int*   adj = (const int*)d_in[3];     // [4096, 4096, 1]
    float* out = (float*)d_out;                 // [4096, 256]

    (void)in_sizes; (void)n_in; (void)out_size;

    dim3 g1(N_NODES / 64, N_HEADS / 2);
    gemm_fused_kernel<<<g1, 256>>>(h, W, a);

    attn_kernel<<<dim3(N_NODES / 32, JSPLIT), 256>>>(adj);

    reduce_kernel<<<(N_NODES * OUT_FEAT / 4) / 256, 256>>>(out);
}